// round 7
// baseline (speedup 1.0000x reference)
#include <cuda_runtime.h>
#include <cuda_bf16.h>

// x: (1,128,56,56) f32   d_in[0]
// W: (64,16,3)     f32   d_in[1]
// out: (1,32,56,56) f32
//
// y[g,k,n,m] = sum_{i<64,j<3} W[i,k,j] * t_pad[g*64+i, n, m+j]
//   t_pad[c,n,s]: s==0||s==57 -> 0; else x[c,n,(s+54)%56]   (fused roll+pad)
// out[g*16+k, (n+1)%56, m] = y[g,k,n,m]                      (fused output roll)

#define C_IN 64
#define K_OUT 16
#define HW 56
#define XS_STRIDE 60          // 58 used + 2 pad -> 240B rows, 16B-aligned
#define NSPLIT 4
#define I_PER (C_IN / NSPLIT) // 16
#define MG 7                  // m-groups of 8 columns
#define NTHREADS (NSPLIT * K_OUT * MG)   // 448

__global__ __launch_bounds__(NTHREADS, 1)
void shifted_gconv_kernel(const float* __restrict__ x,
                          const float* __restrict__ W,
                          float* __restrict__ out)
{
    const int n = blockIdx.x;   // conv row 0..55
    const int g = blockIdx.y;   // group 0..1
    const int tid = threadIdx.x;

    __shared__ __align__(16) float xs[C_IN * XS_STRIDE];      // 15360 B
    __shared__ __align__(16) float wsp[C_IN * K_OUT * 4];     // 16384 B (j padded 3->4)
    __shared__ __align__(16) float red[NSPLIT][K_OUT * MG * 8]; // 4*896*4 = 14336 B

    // ---- stage W into padded layout: wsp[i*64 + k*4 + j] ----
    for (int idx = tid; idx < C_IN * K_OUT * 3; idx += NTHREADS) {
        const int i = idx / 48;
        const int rem = idx - i * 48;
        const int k = rem / 3;
        const int j = rem - k * 3;
        wsp[i * 64 + k * 4 + j] = W[idx];
    }

    // ---- stage x slab for this (g, n): fused roll(+1) + pad ----
    const float* xrow = x + (size_t)g * C_IN * HW * HW + (size_t)n * HW;
    for (int idx = tid; idx < C_IN * HW; idx += NTHREADS) {
        const int i = idx / HW;
        const int w = idx - i * HW;
        const int s = (w + 2 <= 56) ? (w + 2) : (w - 54);
        xs[i * XS_STRIDE + s] = xrow[(size_t)i * HW * HW + w];
    }
    // zero pad columns (s = 0 and s = 57)
    for (int i = tid; i < C_IN; i += NTHREADS) {
        xs[i * XS_STRIDE + 0]  = 0.f;
        xs[i * XS_STRIDE + 57] = 0.f;
    }
    __syncthreads();

    // ---- compute: thread = (isplit, k, mg); 8 consecutive m each ----
    const int isplit = tid / (K_OUT * MG);          // 0..3
    const int r      = tid - isplit * (K_OUT * MG); // 0..111
    const int k      = r / MG;                      // 0..15
    const int mg     = r - k * MG;                  // 0..6
    const int m0     = mg * 8;

    float acc[8];
    #pragma unroll
    for (int q = 0; q < 8; q++) acc[q] = 0.f;

    const int ibase = isplit * I_PER;

    #pragma unroll
    for (int ii = 0; ii < I_PER; ii++) {
        const int i = ibase + ii;
        const float* xr = xs + i * XS_STRIDE + m0;   // 16B-aligned

        float4 va = *reinterpret_cast<const float4*>(xr);
        float4 vb = *reinterpret_cast<const float4*>(xr + 4);
        float v8 = xr[8];
        float v9 = xr[9];
        float v[10] = {va.x, va.y, va.z, va.w, vb.x, vb.y, vb.z, vb.w, v8, v9};

        float4 w4 = *reinterpret_cast<const float4*>(wsp + i * 64 + k * 4);

        #pragma unroll
        for (int q = 0; q < 8; q++)
            acc[q] = fmaf(w4.x, v[q], fmaf(w4.y, v[q + 1], fmaf(w4.z, v[q + 2], acc[q])));
    }

    // ---- cross-split reduction in smem ----
    #pragma unroll
    for (int q = 0; q < 8; q++)
        red[isplit][r * 8 + q] = acc[q];
    __syncthreads();

    if (tid < K_OUT * MG) {
        float4 f0a = *reinterpret_cast<const float4*>(&red[0][tid * 8]);
        float4 f0b = *reinterpret_cast<const float4*>(&red[0][tid * 8 + 4]);
        float4 f1a = *reinterpret_cast<const float4*>(&red[1][tid * 8]);
        float4 f1b = *reinterpret_cast<const float4*>(&red[1][tid * 8 + 4]);
        float4 f2a = *reinterpret_cast<const float4*>(&red[2][tid * 8]);
        float4 f2b = *reinterpret_cast<const float4*>(&red[2][tid * 8 + 4]);
        float4 f3a = *reinterpret_cast<const float4*>(&red[3][tid * 8]);
        float4 f3b = *reinterpret_cast<const float4*>(&red[3][tid * 8 + 4]);

        float4 oa, ob;
        oa.x = (f0a.x + f1a.x) + (f2a.x + f3a.x);
        oa.y = (f0a.y + f1a.y) + (f2a.y + f3a.y);
        oa.z = (f0a.z + f1a.z) + (f2a.z + f3a.z);
        oa.w = (f0a.w + f1a.w) + (f2a.w + f3a.w);
        ob.x = (f0b.x + f1b.x) + (f2b.x + f3b.x);
        ob.y = (f0b.y + f1b.y) + (f2b.y + f3b.y);
        ob.z = (f0b.z + f1b.z) + (f2b.z + f3b.z);
        ob.w = (f0b.w + f1b.w) + (f2b.w + f3b.w);

        // store with fused output roll along H: row n -> row (n+1)%56
        const int nh = (n + 1 == HW) ? 0 : n + 1;
        const int kk  = tid / MG;
        const int mm0 = (tid - kk * MG) * 8;
        float* orow = out + ((size_t)(g * K_OUT + kk) * HW + nh) * HW + mm0;
        *reinterpret_cast<float4*>(orow)     = oa;
        *reinterpret_cast<float4*>(orow + 4) = ob;
    }
}

extern "C" void kernel_launch(void* const* d_in, const int* in_sizes, int n_in,
                              void* d_out, int out_size)
{
    const float* x = (const float*)d_in[0];
    const float* W = (const float*)d_in[1];
    float* out = (float*)d_out;

    dim3 grid(HW, 2);   // 56 rows x 2 groups = 112 blocks
    shifted_gconv_kernel<<<grid, NTHREADS>>>(x, W, out);
}

// round 11
// speedup vs baseline: 1.3107x; 1.3107x over previous
#include <cuda_runtime.h>
#include <cuda_bf16.h>

// x: (1,128,56,56) f32   d_in[0]
// W: (64,16,3)     f32   d_in[1]
// out: (1,32,56,56) f32
//
// y[g,k,n,m] = sum_{i<64,j<3} W[i,k,j] * t_pad[g*64+i, n, m+j]
//   t_pad[c,n,s]: s==0||s==57 -> 0; else x[c,n,(s+54)%56]   (fused roll+pad)
// out[g*16+k, (n+1)%56, m] = y[g,k,n,m]                      (fused output roll)

#define C_IN 64
#define K_OUT 16
#define HW 56
#define XS_STRIDE 58
#define NSPLIT 8                 // channel-split factor
#define I_PER (C_IN / NSPLIT)    // 8 channels per split
#define NTHREADS (NSPLIT * 128)  // 1024

__global__ __launch_bounds__(NTHREADS, 1)
void shifted_gconv_kernel(const float* __restrict__ x,
                          const float* __restrict__ W,
                          float* __restrict__ out)
{
    const int n = blockIdx.x;   // conv row 0..55
    const int g = blockIdx.y;   // group 0..1
    const int tid = threadIdx.x;

    __shared__ float xs[C_IN * XS_STRIDE];   // 14848 B
    __shared__ float ws[C_IN * K_OUT * 3];   // 12288 B
    __shared__ float red[4][128 * 7];        // 14336 B  (total 41472 B < 48K)

    // ---- stage W, coalesced, layout unchanged ----
    #pragma unroll
    for (int idx = tid; idx < C_IN * K_OUT * 3; idx += NTHREADS)
        ws[idx] = W[idx];

    // ---- stage x slab for this (g, n): fused roll(+1) + pad ----
    const float* xrow = x + (size_t)g * C_IN * HW * HW + (size_t)n * HW;
    #pragma unroll
    for (int idx = tid; idx < C_IN * HW; idx += NTHREADS) {
        const int i = idx / HW;
        const int w = idx - i * HW;
        const int s = (w + 2 <= 56) ? (w + 2) : (w - 54);
        xs[i * XS_STRIDE + s] = xrow[(size_t)i * HW * HW + w];
    }
    // zero pad columns (s = 0 and s = 57)
    if (tid < C_IN) {
        xs[tid * XS_STRIDE + 0]  = 0.f;
        xs[tid * XS_STRIDE + 57] = 0.f;
    }
    __syncthreads();

    // ---- compute: thread = (isplit, k, m-octant); 7 consecutive m each ----
    const int isplit = tid >> 7;        // 0..7
    const int r  = tid & 127;           // 0..127
    const int k  = r >> 3;              // 0..15
    const int mg = r & 7;               // 0..7
    const int m0 = mg * 7;

    float acc[7];
    #pragma unroll
    for (int q = 0; q < 7; q++) acc[q] = 0.f;

    const float* wp = ws + k * 3;
    const int ibase = isplit * I_PER;

    #pragma unroll
    for (int ii = 0; ii < I_PER; ii++) {
        const int i = ibase + ii;
        const float* xr = xs + i * XS_STRIDE + m0;
        float v[9];
        #pragma unroll
        for (int q = 0; q < 9; q++) v[q] = xr[q];   // broadcast + conflict-free

        const float w0 = wp[i * 48 + 0];
        const float w1 = wp[i * 48 + 1];
        const float w2 = wp[i * 48 + 2];

        #pragma unroll
        for (int q = 0; q < 7; q++)
            acc[q] = fmaf(w0, v[q], fmaf(w1, v[q + 1], fmaf(w2, v[q + 2], acc[q])));
    }

    // ---- two-stage cross-split reduction (stride-7: conflict-free) ----
    // stage 1: splits 4..7 spill
    if (isplit >= 4) {
        #pragma unroll
        for (int q = 0; q < 7; q++)
            red[isplit - 4][r * 7 + q] = acc[q];
    }
    __syncthreads();
    // stage 2: splits 0..3 accumulate partner, write combined partial
    if (isplit < 4) {
        #pragma unroll
        for (int q = 0; q < 7; q++)
            acc[q] += red[isplit][r * 7 + q];
        #pragma unroll
        for (int q = 0; q < 7; q++)
            red[isplit][r * 7 + q] = acc[q];
    }
    __syncthreads();

    // final: 128 threads sum 4 partials and store
    if (tid < 128) {
        float fin[7];
        #pragma unroll
        for (int q = 0; q < 7; q++)
            fin[q] = (red[0][tid * 7 + q] + red[1][tid * 7 + q])
                   + (red[2][tid * 7 + q] + red[3][tid * 7 + q]);

        // store with fused output roll along H: row n -> row (n+1)%56
        const int nh = (n + 1 == HW) ? 0 : n + 1;
        const int kk  = tid >> 3;
        const int mm0 = (tid & 7) * 7;
        float* orow = out + ((size_t)(g * K_OUT + kk) * HW + nh) * HW + mm0;
        #pragma unroll
        for (int q = 0; q < 7; q++) orow[q] = fin[q];
    }
}

extern "C" void kernel_launch(void* const* d_in, const int* in_sizes, int n_in,
                              void* d_out, int out_size)
{
    const float* x = (const float*)d_in[0];
    const float* W = (const float*)d_in[1];
    float* out = (float*)d_out;

    dim3 grid(HW, 2);   // 56 rows x 2 groups = 112 blocks
    shifted_gconv_kernel<<<grid, NTHREADS>>>(x, W, out);
}